// round 11
// baseline (speedup 1.0000x reference)
#include <cuda_runtime.h>
#include <cuda_bf16.h>
#include <math.h>
#include <stdint.h>

// ---------------------------------------------------------------------------
// Problem constants
// ---------------------------------------------------------------------------
#define BATCH 4
#define SEQ   2048
#define DIM   768
#define NTOK  (BATCH * SEQ)          // 8192
#define NTHREADS 256
#define SCALE 0.03608439182435161f   // 1/sqrt(768)

// bf16 GEMM tiling (M GEMM only): 128x128 tile, K chunk 32 bf16, SW64
#define BK 32
#define TILE_B  8192
#define STAGE_B (4 * TILE_B)         // 32 KB
#define SMEM_BYTES (2 * STAGE_B)     // 64 KB

// tf32 tiling: 128x128 CTA tile, K chunk of 32 fp32 (128B rows, SW128)
#define BK2 32
#define PV_TILE_B  16384
#define PV_STAGE_B (2 * PV_TILE_B)
#define PV_SMEM    (2 * PV_STAGE_B)  // 64 KB

#define SWZ(o)   ((o) ^ ((((uint32_t)(o)) >> 3) & 0x70))   // SW128
#define SWZ64(o) ((o) ^ ((((uint32_t)(o)) >> 3) & 0x30))   // SW64

// ---------------------------------------------------------------------------
// Scratch (__device__ globals; referenced ONLY from device code)
// ---------------------------------------------------------------------------
__device__ __align__(128) float         g_xt[NTOK * DIM];      // x tf32-rounded
__device__ __align__(128) __nv_bfloat16 g_wqTh[DIM * DIM], g_wqTl[DIM * DIM];
__device__ __align__(128) __nv_bfloat16 g_wkTh[DIM * DIM], g_wkTl[DIM * DIM];
__device__ __align__(128) float         g_wvt[DIM * DIM];      // wv tf32-rounded
__device__ __align__(128) float         g_mt[DIM * DIM];       // Mrow tf32-rounded
__device__ __align__(128) float         g_yt[NTOK * DIM];      // Y tf32-rounded
__device__ __align__(128) float         g_vt[DIM * NTOK];      // V^T tf32-rounded
__device__ __align__(128) float         g_s[(size_t)BATCH * SEQ * SEQ];

// ---------------------------------------------------------------------------
// PTX helpers
// ---------------------------------------------------------------------------
__device__ __forceinline__ uint32_t smem_u32(const void* p) {
    uint32_t a;
    asm("{ .reg .u64 t; cvta.to.shared.u64 t, %1; cvt.u32.u64 %0, t; }"
        : "=r"(a) : "l"(p));
    return a;
}
__device__ __forceinline__ void cp16(uint32_t dst, const void* src) {
    asm volatile("cp.async.cg.shared.global [%0], [%1], 16;" :: "r"(dst), "l"(src));
}
__device__ __forceinline__ void cp_commit() {
    asm volatile("cp.async.commit_group;" ::: "memory");
}
template <int N>
__device__ __forceinline__ void cp_wait() {
    asm volatile("cp.async.wait_group %0;" :: "n"(N) : "memory");
}
__device__ __forceinline__ void ldsm4(uint32_t addr, uint32_t* r) {
    asm volatile("ldmatrix.sync.aligned.m8n8.x4.shared.b16 {%0,%1,%2,%3}, [%4];"
                 : "=r"(r[0]), "=r"(r[1]), "=r"(r[2]), "=r"(r[3]) : "r"(addr));
}
__device__ __forceinline__ void ldsm2(uint32_t addr, uint32_t* r) {
    asm volatile("ldmatrix.sync.aligned.m8n8.x2.shared.b16 {%0,%1}, [%2];"
                 : "=r"(r[0]), "=r"(r[1]) : "r"(addr));
}
__device__ __forceinline__ void mma16816(float* d, const uint32_t* a, const uint32_t* b) {
    asm volatile(
        "mma.sync.aligned.m16n8k16.row.col.f32.bf16.bf16.f32 "
        "{%0,%1,%2,%3}, {%4,%5,%6,%7}, {%8,%9}, {%0,%1,%2,%3};"
        : "+f"(d[0]), "+f"(d[1]), "+f"(d[2]), "+f"(d[3])
        : "r"(a[0]), "r"(a[1]), "r"(a[2]), "r"(a[3]), "r"(b[0]), "r"(b[1]));
}
__device__ __forceinline__ void mma1688t(float* d, const uint32_t* a, const uint32_t* b) {
    asm volatile(
        "mma.sync.aligned.m16n8k8.row.col.f32.tf32.tf32.f32 "
        "{%0,%1,%2,%3}, {%4,%5,%6,%7}, {%8,%9}, {%0,%1,%2,%3};"
        : "+f"(d[0]), "+f"(d[1]), "+f"(d[2]), "+f"(d[3])
        : "r"(a[0]), "r"(a[1]), "r"(a[2]), "r"(a[3]), "r"(b[0]), "r"(b[1]));
}
__device__ __forceinline__ float to_tf32(float x) {
    float r;
    asm("cvt.rna.tf32.f32 %0, %1;" : "=f"(r) : "f"(x));
    return r;
}

// ---------------------------------------------------------------------------
// 128x128 NT GEMM tile, split-bf16 3-term, BK=32, SW64.
// Used ONLY for the tiny M GEMM. Epilogue: tf32-rounded fp32 out.
// ---------------------------------------------------------------------------
__device__ __forceinline__ void gemm_core_m(
    const __nv_bfloat16* __restrict__ Ah, const __nv_bfloat16* __restrict__ Al, int lda,
    const __nv_bfloat16* __restrict__ Bh, const __nv_bfloat16* __restrict__ Bl, int ldb,
    int m0, int n0, int nIter,
    float* __restrict__ Of, int ldc)
{
    extern __shared__ char smem[];
    const uint32_t sbase = smem_u32(smem);
    const int tid  = threadIdx.x;
    const int lane = tid & 31;
    const int wid  = tid >> 5;
    const int wm   = wid >> 2;
    const int wn   = wid & 3;

    const __nv_bfloat16* A0h = Ah + (size_t)m0 * lda;
    const __nv_bfloat16* A0l = Al + (size_t)m0 * lda;
    const __nv_bfloat16* B0h = Bh + (size_t)n0 * ldb;
    const __nv_bfloat16* B0l = Bl + (size_t)n0 * ldb;

    auto load_tile = [&](int it) {
        const uint32_t db = sbase + (uint32_t)(it & 1) * STAGE_B;
        const int k0 = it * BK;
#pragma unroll
        for (int i = 0; i < 2; i++) {
            const int c = tid + i * NTHREADS;
            const int row = c >> 2, ch = c & 3;
            const uint32_t so = SWZ64((uint32_t)(row * 64 + ch * 16));
            const size_t ga = (size_t)row * lda + k0 + ch * 8;
            const size_t gb = (size_t)row * ldb + k0 + ch * 8;
            cp16(db + so,              A0h + ga);
            cp16(db + TILE_B + so,     A0l + ga);
            cp16(db + 2 * TILE_B + so, B0h + gb);
            cp16(db + 3 * TILE_B + so, B0l + gb);
        }
        cp_commit();
    };

    float acc[4][4][4];
#pragma unroll
    for (int i = 0; i < 4; i++)
#pragma unroll
        for (int j = 0; j < 4; j++)
#pragma unroll
            for (int v = 0; v < 4; v++) acc[i][j][v] = 0.0f;

    const uint32_t a_l = ((uint32_t)(lane & 15) << 6) + ((uint32_t)(lane >> 4) << 4);
    const uint32_t b_l = ((uint32_t)(lane & 7) << 6) + ((uint32_t)((lane >> 3) & 1) << 4);

    load_tile(0);
    load_tile(1);

    for (int it = 0; it < nIter; ++it) {
        if (it + 1 < nIter) cp_wait<1>(); else cp_wait<0>();
        __syncthreads();

        const uint32_t db = sbase + (uint32_t)(it & 1) * STAGE_B;
#pragma unroll
        for (int ks = 0; ks < 2; ks++) {
            uint32_t ah[4][4], al_[4][4], bh[4][2], bl_[4][2];
#pragma unroll
            for (int fm = 0; fm < 4; fm++) {
                const uint32_t sw = SWZ64(((uint32_t)(wm * 64 + fm * 16) << 6) +
                                          (uint32_t)(ks * 32) + a_l);
                ldsm4(db + sw, ah[fm]);
                ldsm4(db + TILE_B + sw, al_[fm]);
            }
#pragma unroll
            for (int fn = 0; fn < 4; fn++) {
                const uint32_t sw = SWZ64(((uint32_t)(wn * 32 + fn * 8) << 6) +
                                          (uint32_t)(ks * 32) + b_l);
                ldsm2(db + 2 * TILE_B + sw, bh[fn]);
                ldsm2(db + 3 * TILE_B + sw, bl_[fn]);
            }
#pragma unroll
            for (int fm = 0; fm < 4; fm++)
#pragma unroll
                for (int fn = 0; fn < 4; fn++)
                    mma16816(acc[fm][fn], ah[fm], bh[fn]);
#pragma unroll
            for (int fm = 0; fm < 4; fm++)
#pragma unroll
                for (int fn = 0; fn < 4; fn++)
                    mma16816(acc[fm][fn], ah[fm], bl_[fn]);
#pragma unroll
            for (int fm = 0; fm < 4; fm++)
#pragma unroll
                for (int fn = 0; fn < 4; fn++)
                    mma16816(acc[fm][fn], al_[fm], bh[fn]);
        }
        __syncthreads();
        if (it + 2 < nIter) load_tile(it + 2);
    }

    const int er = lane >> 2;
    const int ec = (lane & 3) * 2;
#pragma unroll
    for (int fm = 0; fm < 4; fm++) {
#pragma unroll
        for (int fn = 0; fn < 4; fn++) {
            const int r0 = m0 + wm * 64 + fm * 16 + er;
            const int r1 = r0 + 8;
            const int c  = n0 + wn * 32 + fn * 8 + ec;
            *(float2*)(Of + (size_t)r0 * ldc + c) =
                make_float2(to_tf32(acc[fm][fn][0]), to_tf32(acc[fm][fn][1]));
            *(float2*)(Of + (size_t)r1 * ldc + c) =
                make_float2(to_tf32(acc[fm][fn][2]), to_tf32(acc[fm][fn][3]));
        }
    }
}

// ---------------------------------------------------------------------------
// 128x128 NT GEMM tile, single-term TF32, SW128, ldmatrix fragment loads,
// SOFTWARE-PIPELINED fragments: ks+1's LDSMs issue before ks's MMAs so the
// tensor pipe always has dependency-free work while LDSM completes.
// ROUND 1: round output to tf32.  ROUND 0: plain fp32 out.
// ---------------------------------------------------------------------------
template <int ROUND>
__device__ __forceinline__ void tf32_core(
    const float* __restrict__ A, int lda,
    const float* __restrict__ B, int ldb,
    int m0, int n0, int nIter,
    float* __restrict__ C, int ldc)
{
    extern __shared__ char smem[];
    const uint32_t sbase = smem_u32(smem);
    const int tid  = threadIdx.x;
    const int lane = tid & 31;
    const int wid  = tid >> 5;
    const int wm   = wid >> 2;
    const int wn   = wid & 3;

    const float* A0 = A + (size_t)m0 * lda;
    const float* B0 = B + (size_t)n0 * ldb;

    auto load_tile = [&](int it) {
        const uint32_t db = sbase + (uint32_t)(it & 1) * PV_STAGE_B;
        const int k0 = it * BK2;
#pragma unroll
        for (int i = 0; i < 4; i++) {
            const int c = tid + i * NTHREADS;
            const int row = c >> 3, ch = c & 7;
            const uint32_t so = SWZ((uint32_t)(row * 128 + ch * 16));
            cp16(db + so,             A0 + (size_t)row * lda + k0 + ch * 4);
            cp16(db + PV_TILE_B + so, B0 + (size_t)row * ldb + k0 + ch * 4);
        }
        cp_commit();
    };

    float acc[4][4][4];
#pragma unroll
    for (int i = 0; i < 4; i++)
#pragma unroll
        for (int j = 0; j < 4; j++)
#pragma unroll
            for (int v = 0; v < 4; v++) acc[i][j][v] = 0.0f;

    const uint32_t a_l = ((uint32_t)(lane & 15) << 7) + ((uint32_t)(lane >> 4) << 4);
    const uint32_t b_l = ((uint32_t)(lane & 7) << 7) + ((uint32_t)((lane >> 3) & 1) << 4);

    load_tile(0);
    load_tile(1);

    uint32_t a[2][4][4], bb[2][4][2];   // double-buffered fragments

    for (int it = 0; it < nIter; ++it) {
        if (it + 1 < nIter) cp_wait<1>(); else cp_wait<0>();
        __syncthreads();

        const uint32_t db = sbase + (uint32_t)(it & 1) * PV_STAGE_B;

        auto load_frag = [&](int ks, int pb) {
#pragma unroll
            for (int fm = 0; fm < 4; fm++) {
                const uint32_t sw = SWZ(((uint32_t)(wm * 64 + fm * 16) << 7) +
                                        (uint32_t)(ks * 32) + a_l);
                ldsm4(db + sw, a[pb][fm]);
            }
#pragma unroll
            for (int fn = 0; fn < 4; fn++) {
                const uint32_t sw = SWZ(((uint32_t)(wn * 32 + fn * 8) << 7) +
                                        (uint32_t)(ks * 32) + b_l);
                ldsm2(db + PV_TILE_B + sw, bb[pb][fn]);
            }
        };

        load_frag(0, 0);
#pragma unroll
        for (int ks = 0; ks < 4; ks++) {
            const int cur = ks & 1;
            if (ks < 3) load_frag(ks + 1, cur ^ 1);
#pragma unroll
            for (int fm = 0; fm < 4; fm++)
#pragma unroll
                for (int fn = 0; fn < 4; fn++)
                    mma1688t(acc[fm][fn], a[cur][fm], bb[cur][fn]);
        }
        __syncthreads();
        if (it + 2 < nIter) load_tile(it + 2);
    }

    const int er = lane >> 2;
    const int ec = (lane & 3) * 2;
#pragma unroll
    for (int fm = 0; fm < 4; fm++) {
#pragma unroll
        for (int fn = 0; fn < 4; fn++) {
            const int r0 = m0 + wm * 64 + fm * 16 + er;
            const int r1 = r0 + 8;
            const int c  = n0 + wn * 32 + fn * 8 + ec;
            if (ROUND) {
                *(float2*)(C + (size_t)r0 * ldc + c) =
                    make_float2(to_tf32(acc[fm][fn][0]), to_tf32(acc[fm][fn][1]));
                *(float2*)(C + (size_t)r1 * ldc + c) =
                    make_float2(to_tf32(acc[fm][fn][2]), to_tf32(acc[fm][fn][3]));
            } else {
                *(float2*)(C + (size_t)r0 * ldc + c) = make_float2(acc[fm][fn][0], acc[fm][fn][1]);
                *(float2*)(C + (size_t)r1 * ldc + c) = make_float2(acc[fm][fn][2], acc[fm][fn][3]);
            }
        }
    }
}

// ---------------------------------------------------------------------------
// Kernel 0: convert. x -> xt; wv -> wvt (both tf32-rounded fp32).
// ---------------------------------------------------------------------------
#define NX4 (NTOK * DIM / 4)
#define NW4 (DIM * DIM / 4)

__global__ __launch_bounds__(NTHREADS)
void convert_kernel(const float* __restrict__ x, const float* __restrict__ wv)
{
    const int i = blockIdx.x * NTHREADS + threadIdx.x;
    if (i < NX4) {
        const float4 v = ((const float4*)x)[i];
        ((float4*)g_xt)[i] = make_float4(to_tf32(v.x), to_tf32(v.y),
                                         to_tf32(v.z), to_tf32(v.w));
    } else if (i < NX4 + NW4) {
        const int j = i - NX4;
        const float4 v = ((const float4*)wv)[j];
        ((float4*)g_wvt)[j] = make_float4(to_tf32(v.x), to_tf32(v.y),
                                          to_tf32(v.z), to_tf32(v.w));
    }
}

// ---------------------------------------------------------------------------
// Kernel 1: tiled transpose wq, wk -> bf16 hi/lo pairs of W^T.
// ---------------------------------------------------------------------------
__global__ __launch_bounds__(NTHREADS)
void transpose_w_kernel(const float* __restrict__ wq, const float* __restrict__ wk)
{
    __shared__ float t[32][33];
    const float* src = blockIdx.z ? wk : wq;
    __nv_bfloat16* oh = blockIdx.z ? g_wkTh : g_wqTh;
    __nv_bfloat16* ol = blockIdx.z ? g_wkTl : g_wqTl;
    const int tx = threadIdx.x & 31, ty = threadIdx.x >> 5;
    const int c0 = blockIdx.x * 32, r0 = blockIdx.y * 32;
#pragma unroll
    for (int i = 0; i < 4; i++)
        t[ty + i * 8][tx] = src[(size_t)(r0 + ty + i * 8) * DIM + c0 + tx];
    __syncthreads();
#pragma unroll
    for (int i = 0; i < 4; i++) {
        const int d = c0 + ty + i * 8;
        const int e = r0 + tx;
        const float v = t[tx][ty + i * 8];
        const __nv_bfloat16 h = __float2bfloat16(v);
        oh[(size_t)d * DIM + e] = h;
        ol[(size_t)d * DIM + e] = __float2bfloat16(v - __bfloat162float(h));
    }
}

// ---------------------------------------------------------------------------
// Kernel 2: fused V + M.
//   CTA < 384:  V^T = Wv X^T, single-term tf32, out g_vt (tf32-rounded)
//   CTA >= 384: Mrow = Wk^T x Wq^T (3-term bf16), out g_mt (tf32-rounded fp32)
// ---------------------------------------------------------------------------
__global__ __launch_bounds__(NTHREADS)
void vm_kernel()
{
    const int cta = blockIdx.x;
    if (cta < 384) {
        const int mi = cta / 64, ni = cta % 64;
        tf32_core<1>(g_wvt, DIM, g_xt, DIM,
                     mi * 128, ni * 128, DIM / BK2, g_vt, NTOK);
    } else {
        const int c2 = cta - 384;
        const int mi = c2 / 6, ni = c2 % 6;
        gemm_core_m(g_wkTh, g_wkTl, DIM, g_wqTh, g_wqTl, DIM,
                    mi * 128, ni * 128, DIM / BK, g_mt, DIM);
    }
}

// ---------------------------------------------------------------------------
// Kernel 3: Y = X * Mrow^T, single-term TF32, tf32-rounded out. grid (6,64).
// ---------------------------------------------------------------------------
__global__ __launch_bounds__(NTHREADS)
void y_kernel()
{
    tf32_core<1>(g_xt, DIM, g_mt, DIM,
                 blockIdx.y * 128, blockIdx.x * 128, DIM / BK2,
                 g_yt, DIM);
}

// ---------------------------------------------------------------------------
// Kernel 4: scores S = Y X^T, single-term TF32, packed triangle grid (136,4).
// ---------------------------------------------------------------------------
__global__ __launch_bounds__(NTHREADS)
void scores_kernel()
{
    const int t = blockIdx.x;
    int mi = (int)((sqrtf(8.0f * (float)t + 1.0f) - 1.0f) * 0.5f);
    while ((mi + 1) * (mi + 2) / 2 <= t) mi++;
    while (mi * (mi + 1) / 2 > t) mi--;
    const int ni = t - mi * (mi + 1) / 2;

    const int b = blockIdx.y;
    const size_t o = (size_t)b * SEQ * DIM;
    tf32_core<0>(g_yt + o, DIM, g_xt + o, DIM,
                 mi * 128, ni * 128, DIM / BK2,
                 g_s + (size_t)b * SEQ * SEQ, SEQ);
}

// ---------------------------------------------------------------------------
// Kernel 5: causal softmax in place (tf32-rounded probs, bounded I/O).
// ---------------------------------------------------------------------------
__global__ __launch_bounds__(NTHREADS)
void softmax_kernel()
{
    const int q = blockIdx.x, b = blockIdx.y;
    float* row = g_s + ((size_t)b * SEQ + q) * SEQ;
    const int nvalid = q + 1;
    const int zlim = (q & ~127) + 128;
    const int tid = threadIdx.x, lane = tid & 31, wid = tid >> 5;

    __shared__ float sred[8];

    const int e0 = 4 * tid, e1 = 4 * (tid + 256);
    float4 v0 = (e0 < nvalid) ? ((const float4*)row)[tid]
                              : make_float4(0.f, 0.f, 0.f, 0.f);
    float4 v1 = (e1 < nvalid) ? ((const float4*)row)[tid + 256]
                              : make_float4(0.f, 0.f, 0.f, 0.f);

    float f[8] = {v0.x, v0.y, v0.z, v0.w, v1.x, v1.y, v1.z, v1.w};
    int   ei[8] = {e0, e0 + 1, e0 + 2, e0 + 3, e1, e1 + 1, e1 + 2, e1 + 3};

    float mx = -INFINITY;
#pragma unroll
    for (int j = 0; j < 8; j++)
        if (ei[j] < nvalid) mx = fmaxf(mx, f[j]);
#pragma unroll
    for (int o = 16; o > 0; o >>= 1)
        mx = fmaxf(mx, __shfl_xor_sync(0xffffffffu, mx, o));
    if (lane == 0) sred[wid] = mx;
    __syncthreads();
    mx = sred[0];
#pragma unroll
    for (int w = 1; w < 8; w++) mx = fmaxf(mx, sred[w]);

    float sum = 0.0f;
#pragma unroll
    for (int j = 0; j < 8; j++) {
        f[j] = (ei[j] < nvalid) ? expf((f[j] - mx) * SCALE) : 0.0f;
        sum += f[j];
    }
#pragma unroll
    for (int o = 16; o > 0; o >>= 1)
        sum += __shfl_xor_sync(0xffffffffu, sum, o);
    __syncthreads();
    if (lane == 0) sred[wid] = sum;
    __syncthreads();
    sum = 0.0f;
#pragma unroll
    for (int w = 0; w < 8; w++) sum += sred[w];
    const float inv = 1.0f / sum;

    if (e0 < zlim)
        ((float4*)row)[tid] = make_float4(to_tf32(f[0] * inv), to_tf32(f[1] * inv),
                                          to_tf32(f[2] * inv), to_tf32(f[3] * inv));
    if (e1 < zlim)
        ((float4*)row)[tid + 256] = make_float4(to_tf32(f[4] * inv), to_tf32(f[5] * inv),
                                                to_tf32(f[6] * inv), to_tf32(f[7] * inv));
}

// ---------------------------------------------------------------------------
// Kernel 6: O = P V via V^T, single-term tf32, k bounded by causal diagonal.
// ---------------------------------------------------------------------------
__global__ __launch_bounds__(NTHREADS)
void pv_kernel(float* __restrict__ out)
{
    const int b = blockIdx.z;
    const int m0 = blockIdx.y * 128, n0 = blockIdx.x * 128;
    tf32_core<0>(g_s + (size_t)b * SEQ * SEQ, SEQ,
                 g_vt + (size_t)b * SEQ, NTOK,
                 m0, n0, (m0 + 128) / BK2,
                 out + (size_t)b * SEQ * DIM, DIM);
}

// ---------------------------------------------------------------------------
extern "C" void kernel_launch(void* const* d_in, const int* in_sizes, int n_in,
                              void* d_out, int out_size)
{
    const float* x  = (const float*)d_in[0];
    const float* wq = (const float*)d_in[1];
    const float* wk = (const float*)d_in[2];
    const float* wv = (const float*)d_in[3];
    float* out = (float*)d_out;

    cudaFuncSetAttribute(vm_kernel,     cudaFuncAttributeMaxDynamicSharedMemorySize, PV_SMEM);
    cudaFuncSetAttribute(y_kernel,      cudaFuncAttributeMaxDynamicSharedMemorySize, PV_SMEM);
    cudaFuncSetAttribute(scores_kernel, cudaFuncAttributeMaxDynamicSharedMemorySize, PV_SMEM);
    cudaFuncSetAttribute(pv_kernel,     cudaFuncAttributeMaxDynamicSharedMemorySize, PV_SMEM);

    const int ntot = NX4 + NW4;
    convert_kernel<<<(ntot + NTHREADS - 1) / NTHREADS, NTHREADS>>>(x, wv);
    transpose_w_kernel<<<dim3(24, 24, 2), NTHREADS>>>(wq, wk);
    vm_kernel<<<420, NTHREADS, PV_SMEM>>>();
    y_kernel<<<dim3(DIM / 128, NTOK / 128), NTHREADS, PV_SMEM>>>();
    scores_kernel<<<dim3(136, BATCH), NTHREADS, PV_SMEM>>>();
    softmax_kernel<<<dim3(SEQ, BATCH), NTHREADS>>>();
    pv_kernel<<<dim3(DIM / 128, SEQ / 128, BATCH), NTHREADS, PV_SMEM>>>(out);
}